// round 1
// baseline (speedup 1.0000x reference)
#include <cuda_runtime.h>
#include <cstdint>

typedef unsigned long long ull;

#define Ee   130
#define HE   1040          // H * E
#define TOK  64            // tokens per block

__device__ __forceinline__ ull splat2(float v) {
    ull r;
    asm("mov.b64 %0, {%1, %1};" : "=l"(r) : "r"(__float_as_uint(v)));
    return r;
}
__device__ __forceinline__ void fma2(ull& acc, ull a, ull b) {
    asm("fma.rn.f32x2 %0, %1, %2, %0;" : "+l"(acc) : "l"(a), "l"(b));
}

// ---------------------------------------------------------------------------
// QK kernel: 256 threads. Warp w -> head (w>>1) in 0..3, token-group (w&1).
// Each lane owns one token; computes that head's 64 matvec outputs via
// f32x2 packed FMA with broadcast LDS.64 weight reads.
// Also writes the (head+4) scalar/zero row for its token.
// x_off: 65 for q (uses x2), 0 for k (uses x1).
// use_mid: 0 -> heads>=4 scalar uses s_last (q); 1 -> s_mid (k).
// ---------------------------------------------------------------------------
__global__ void __launch_bounds__(256, 2) qk_kernel(
    const float* __restrict__ x, const float* __restrict__ M,
    const float* __restrict__ Bvec, float* __restrict__ out,
    int x_off, int use_mid)
{
    extern __shared__ float smem[];
    float* wsm = smem;               // [64][258]  W^T, padded to kill STS conflicts
    float* xs  = smem + 64 * 258;    // [TOK][130]
    const int  tid  = threadIdx.x;
    const long tok0 = (long)blockIdx.x * TOK;

    // W^T into smem: wsm[j][r] = M[r*64+j], r=p*64+i in 0..255
    for (int idx = tid; idx < 256 * 64; idx += 256) {
        int r = idx >> 6, j = idx & 63;
        wsm[j * 258 + r] = M[idx];
    }
    const float* xg = x + tok0 * Ee;
    for (int idx = tid; idx < TOK * Ee; idx += 256) xs[idx] = xg[idx];
    __syncthreads();

    const int warp  = tid >> 5, lane = tid & 31;
    const int head  = warp >> 1;
    const int t     = ((warp & 1) << 5) + lane;
    const int obase = head << 6;
    const float* xrow = xs + t * Ee + x_off;

    ull acc[32];
#pragma unroll
    for (int j = 0; j < 32; j++) acc[j] = 0ULL;

#pragma unroll 2
    for (int k = 0; k < 64; k++) {
        ull xx = splat2(xrow[k]);
        const ull* wp = (const ull*)(wsm + k * 258 + obase);
#pragma unroll
        for (int j = 0; j < 32; j++) fma2(acc[j], wp[j], xx);
    }

    float s_last = xs[t * Ee + 129];
    float s_mid  = xs[t * Ee + 64];
    float v129   = s_last * Bvec[head];                       // col 129, head<4
    float v65    = (use_mid ? s_mid : s_last) * Bvec[head + 4]; // col 65, head>=4

    float* orow = out + (tok0 + t) * HE + head * Ee;
    float2 z = make_float2(0.f, 0.f);
    float2* o2 = (float2*)orow;
#pragma unroll
    for (int j = 0; j < 32; j++) o2[j] = z;                   // cols 0..63 = 0
    ull* op = (ull*)(orow + 64);
    op[0] = acc[0] << 32;                                     // (0, y0)
#pragma unroll
    for (int m = 1; m < 32; m++)
        op[m] = (acc[m - 1] >> 32) | (acc[m] << 32);          // (y[2m-1], y[2m])
    op[32] = (acc[31] >> 32) | ((ull)__float_as_uint(v129) << 32); // (y63, v129)

    // head+4 row: all zeros except col 65
    float2* o4 = (float2*)(out + (tok0 + t) * HE + (head + 4) * Ee);
#pragma unroll
    for (int j = 0; j < 65; j++)
        o4[j] = (j == 32) ? make_float2(0.f, v65) : z;
}

// ---------------------------------------------------------------------------
// V kernel: 512 threads, 16 warps -> 8 heads x 2 token-groups. Same matvec.
// Row: cols 0..64 zero, 65..128 = M_v@x1, col 129 zero.
// ---------------------------------------------------------------------------
__global__ void __launch_bounds__(512, 1) v_kernel(
    const float* __restrict__ x, const float* __restrict__ M,
    float* __restrict__ out)
{
    extern __shared__ float smem[];
    float* wsm = smem;               // [64][514]
    float* xs  = smem + 64 * 514;    // [TOK][130]
    const int  tid  = threadIdx.x;
    const long tok0 = (long)blockIdx.x * TOK;

    for (int idx = tid; idx < 512 * 64; idx += 512) {
        int r = idx >> 6, j = idx & 63;
        wsm[j * 514 + r] = M[idx];
    }
    const float* xg = x + tok0 * Ee;
    for (int idx = tid; idx < TOK * Ee; idx += 512) xs[idx] = xg[idx];
    __syncthreads();

    const int warp  = tid >> 5, lane = tid & 31;
    const int head  = warp >> 1;     // 0..7
    const int t     = ((warp & 1) << 5) + lane;
    const int obase = head << 6;
    const float* xrow = xs + t * Ee;

    ull acc[32];
#pragma unroll
    for (int j = 0; j < 32; j++) acc[j] = 0ULL;

#pragma unroll 2
    for (int k = 0; k < 64; k++) {
        ull xx = splat2(xrow[k]);
        const ull* wp = (const ull*)(wsm + k * 514 + obase);
#pragma unroll
        for (int j = 0; j < 32; j++) fma2(acc[j], wp[j], xx);
    }

    float* orow = out + (tok0 + t) * HE + head * Ee;
    float2 z = make_float2(0.f, 0.f);
    float2* o2 = (float2*)orow;
#pragma unroll
    for (int j = 0; j < 32; j++) o2[j] = z;
    ull* op = (ull*)(orow + 64);
    op[0] = acc[0] << 32;
#pragma unroll
    for (int m = 1; m < 32; m++)
        op[m] = (acc[m - 1] >> 32) | (acc[m] << 32);
    op[32] = (acc[31] >> 32);                                 // (y63, 0)
}

extern "C" void kernel_launch(void* const* d_in, const int* in_sizes, int n_in,
                              void* d_out, int out_size)
{
    const float* x  = (const float*)d_in[0];
    const float* Mq = (const float*)d_in[1];
    const float* Bq = (const float*)d_in[2];
    const float* Mk = (const float*)d_in[3];
    const float* Bk = (const float*)d_in[4];
    const float* Mv = (const float*)d_in[5];
    float* out = (float*)d_out;

    const int ntok  = in_sizes[0] / Ee;          // 32768
    const int tiles = (ntok + TOK - 1) / TOK;    // 512
    const long S    = (long)out_size / 3;        // per-output section

    const int smem_qk = (64 * 258 + TOK * Ee) * (int)sizeof(float); // 99328 B
    const int smem_v  = (64 * 514 + TOK * Ee) * (int)sizeof(float); // 164864 B
    cudaFuncSetAttribute(qk_kernel, cudaFuncAttributeMaxDynamicSharedMemorySize, smem_qk);
    cudaFuncSetAttribute(v_kernel,  cudaFuncAttributeMaxDynamicSharedMemorySize, smem_v);

    qk_kernel<<<tiles, 256, smem_qk>>>(x, Mq, Bq, out,         65, 0);
    qk_kernel<<<tiles, 256, smem_qk>>>(x, Mk, Bk, out + S,      0, 1);
    v_kernel <<<tiles, 512, smem_v >>>(x, Mv,     out + 2 * S);
}

// round 4
// speedup vs baseline: 2.2757x; 2.2757x over previous
#include <cuda_runtime.h>
#include <cstdint>

typedef unsigned long long ull;

#define Ee   130
#define HE   1040
#define TOK  32            // tokens per tile
#define WST  66            // weight smem row stride (floats)
#define XST  68            // x smem row stride (floats)
#define NH   4             // heads per launch

__device__ __forceinline__ ull splat2(float v) {
    ull r;
    asm("mov.b64 %0, {%1, %1};" : "=l"(r) : "r"(__float_as_uint(v)));
    return r;
}
__device__ __forceinline__ void fma2(ull& acc, ull a, ull b) {
    asm("fma.rn.f32x2 %0, %1, %2, %0;" : "+l"(acc) : "l"(a), "l"(b));
}
__device__ __forceinline__ ull pack2(uint32_t lo, uint32_t hi) {
    return (ull)lo | ((ull)hi << 32);
}

// ---------------------------------------------------------------------------
// 4 heads per launch, 128 threads, warp w -> head (ho+w). Persistent over
// token tiles; weights staged to smem once. Lane tiling: colg = lane&7 owns
// output cols [8c..8c+7], g = lane>>3 owns tokens {g,4+g,...,28+g}.
// mode: 0=q (partner col65 = s_last*B), 1=k (partner col65 = s_mid*B), 2=v.
// ---------------------------------------------------------------------------
__global__ void __launch_bounds__(128) fused_kernel(
    const float* __restrict__ x, const float* __restrict__ M,
    const float* __restrict__ Bvec, float* __restrict__ out,
    int x_off, int mode, int ho, int ntiles)
{
    extern __shared__ float smem[];
    float* wsm = smem;                   // [NH][64 k][WST]
    float* xs  = smem + NH * 64 * WST;   // [TOK][XST]: 0..63 slice, 64 s_mid, 65 s_last

    const int tid = threadIdx.x;

    // Weights transposed: wsm[h][j][i] = M[h][i][j]
    for (int idx = tid; idx < (NH << 12); idx += 128) {
        int h = idx >> 12, rem = idx & 4095, i = rem >> 6, j = rem & 63;
        wsm[h * (64 * WST) + j * WST + i] = M[idx];
    }

    const int warp = tid >> 5, lane = tid & 31;
    const int colg = lane & 7, g = lane >> 3;
    const int head = ho + warp;
    const float* hw = wsm + warp * (64 * WST);
    const float  bmain = (mode == 2) ? 0.f : Bvec[head];
    const float  bpart = (mode == 2) ? 0.f : Bvec[head + 4];
    const int    sidx  = (mode == 1) ? 64 : 65;

    for (int tile = blockIdx.x; tile < ntiles; tile += gridDim.x) {
        const long tok0 = (long)tile * TOK;
        __syncthreads();                 // protect xs from previous iteration
        const float* xg = x + tok0 * Ee;
        for (int idx = tid; idx < TOK * 66; idx += 128) {
            int t = idx / 66, c = idx - t * 66;
            int src = (c < 64) ? (x_off + c) : ((c == 64) ? 64 : 129);
            xs[t * XST + c] = xg[t * Ee + src];
        }
        __syncthreads();

        ull acc[8][4];
#pragma unroll
        for (int i = 0; i < 8; i++)
#pragma unroll
            for (int c = 0; c < 4; c++) acc[i][c] = 0ULL;

        const float* xsw = xs + g * XST;
#pragma unroll 1
        for (int kc = 0; kc < 16; kc++) {
            ull w[16];
            const float* wp = hw + kc * 4 * WST + colg * 8;
#pragma unroll
            for (int kk = 0; kk < 4; kk++)
#pragma unroll
                for (int c = 0; c < 4; c++)
                    w[kk * 4 + c] = *(const ull*)(wp + kk * WST + 2 * c);
#pragma unroll
            for (int i = 0; i < 8; i++) {
                const float4 xv = *(const float4*)(xsw + i * 4 * XST + kc * 4);
                float xa[4] = {xv.x, xv.y, xv.z, xv.w};
#pragma unroll
                for (int kk = 0; kk < 4; kk++) {
                    ull xx = splat2(xa[kk]);
#pragma unroll
                    for (int c = 0; c < 4; c++) fma2(acc[i][c], w[kk * 4 + c], xx);
                }
            }
        }

        // ---- main head row: cols 64..129 via STG.64, shfl stitches odd offset
#pragma unroll
        for (int i = 0; i < 8; i++) {
            const int t = i * 4 + g;
            float myhi = __uint_as_float((uint32_t)(acc[i][3] >> 32));
            float prev = __shfl_up_sync(0xffffffffu, myhi, 1);
            if (colg == 0) prev = 0.f;
            ull* op = (ull*)(out + (tok0 + t) * HE + head * Ee + 64 + colg * 8);
            op[0] = pack2(__float_as_uint(prev), (uint32_t)acc[i][0]);
            op[1] = pack2((uint32_t)(acc[i][0] >> 32), (uint32_t)acc[i][1]);
            op[2] = pack2((uint32_t)(acc[i][1] >> 32), (uint32_t)acc[i][2]);
            op[3] = pack2((uint32_t)(acc[i][2] >> 32), (uint32_t)acc[i][3]);
            if (colg == 7) {
                float b = bmain * xs[t * XST + 65];   // s_last * B[h] (0 for v)
                op[4] = pack2((uint32_t)(acc[i][3] >> 32), __float_as_uint(b));
            }
        }
        // zeros cols 0..63 of main rows
        for (int idx = lane; idx < TOK * 32; idx += 32) {
            int t = idx >> 5, m = idx & 31;
            ((ull*)(out + (tok0 + t) * HE + head * Ee))[m] = 0ULL;
        }
        // partner rows (heads 4..7, q/k only): zero except col 65
        if (mode < 2) {
            for (int idx = lane; idx < TOK * 65; idx += 32) {
                int t = idx / 65, m = idx - t * 65;
                ull v = 0ULL;
                if (m == 32) {
                    float s = xs[t * XST + sidx];
                    v = (ull)__float_as_uint(s * bpart) << 32;  // (col64=0, col65=s*b)
                }
                ((ull*)(out + (tok0 + t) * HE + (head + 4) * Ee))[m] = v;
            }
        }
    }
}

extern "C" void kernel_launch(void* const* d_in, const int* in_sizes, int n_in,
                              void* d_out, int out_size)
{
    const float* x  = (const float*)d_in[0];
    const float* Mq = (const float*)d_in[1];
    const float* Bq = (const float*)d_in[2];
    const float* Mk = (const float*)d_in[3];
    const float* Bk = (const float*)d_in[4];
    const float* Mv = (const float*)d_in[5];
    float* out = (float*)d_out;

    const int ntok   = in_sizes[0] / Ee;            // 32768
    const int ntiles = (ntok + TOK - 1) / TOK;      // 1024
    const long S     = (long)out_size / 3;

    const int smem = (NH * 64 * WST + TOK * XST) * (int)sizeof(float); // 76,288 B
    cudaFuncSetAttribute(fused_kernel, cudaFuncAttributeMaxDynamicSharedMemorySize, smem);

    fused_kernel<<<296, 128, smem>>>(x, Mq,            Bq, out,         65, 0, 0, ntiles);
    fused_kernel<<<296, 128, smem>>>(x, Mk,            Bk, out + S,      0, 1, 0, ntiles);
    fused_kernel<<<296, 128, smem>>>(x, Mv,            Bq, out + 2 * S,  0, 2, 0, ntiles);
    fused_kernel<<<296, 128, smem>>>(x, Mv + (4 << 12), Bq, out + 2 * S,  0, 2, 4, ntiles);
}

// round 6
// speedup vs baseline: 3.1170x; 1.3697x over previous
#include <cuda_runtime.h>
#include <cstdint>

typedef unsigned long long ull;

#define Ee   130
#define HE   1040
#define TOK  64            // tokens per tile (two 32-token halves)
#define WST  66            // weight smem row stride (floats)
#define XST  68            // x smem row stride (floats)
#define NH   4             // heads per config

__device__ __forceinline__ ull splat2(float v) {
    ull r;
    asm("mov.b64 %0, {%1, %1};" : "=l"(r) : "r"(__float_as_uint(v)));
    return r;
}
__device__ __forceinline__ void fma2(ull& acc, ull a, ull b) {
    asm("fma.rn.f32x2 %0, %1, %2, %0;" : "+l"(acc) : "l"(a), "l"(b));
}
__device__ __forceinline__ ull pack2(uint32_t lo, uint32_t hi) {
    return (ull)lo | ((ull)hi << 32);
}

// ---------------------------------------------------------------------------
// Single launch. cfg = blockIdx.x & 3: 0=q, 1=k, 2=v(heads 0-3), 3=v(heads 4-7).
// 256 threads: warp&3 = head-within-config, warp>>2 = token half of the
// 64-token tile. Weights staged to smem once; persistent loop over tiles.
// Lane tiling: colg = lane&7 owns cols [8c..8c+7], g = lane>>3 owns 8 tokens.
// ---------------------------------------------------------------------------
__global__ void __launch_bounds__(256, 2) fused_kernel(
    const float* __restrict__ x,
    const float* __restrict__ Mq, const float* __restrict__ Bq,
    const float* __restrict__ Mk, const float* __restrict__ Bk,
    const float* __restrict__ Mv,
    float* __restrict__ out, long S, int ntiles, int nbper)
{
    extern __shared__ float smem[];
    float* wsm = smem;                   // [NH][64 k][WST]
    float* xs  = smem + NH * 64 * WST;   // [TOK][XST]: 0..63 slice, 64 s_mid, 65 s_last

    const int cfg = blockIdx.x & 3;
    const int bset = blockIdx.x >> 2;

    const float* M;  const float* Bv = Bq;
    float* ob;  int x_off, mode, ho;
    if (cfg == 0)      { M = Mq;            ob = out;         x_off = 65; mode = 0; ho = 0; Bv = Bq; }
    else if (cfg == 1) { M = Mk;            ob = out + S;     x_off = 0;  mode = 1; ho = 0; Bv = Bk; }
    else if (cfg == 2) { M = Mv;            ob = out + 2 * S; x_off = 0;  mode = 2; ho = 0; }
    else               { M = Mv + (4 << 12); ob = out + 2 * S; x_off = 0;  mode = 2; ho = 4; }

    const int tid = threadIdx.x;

    // Weights transposed: wsm[h][j][i] = M[h][i][j]
    for (int idx = tid; idx < (NH << 12); idx += 256) {
        int h = idx >> 12, rem = idx & 4095, i = rem >> 6, j = rem & 63;
        wsm[h * (64 * WST) + j * WST + i] = M[idx];
    }

    const int warp = tid >> 5, lane = tid & 31;
    const int hw_i = warp & 3, half = warp >> 2;
    const int colg = lane & 7, g = lane >> 3;
    const int head = ho + hw_i;
    const int toff = half << 5;          // 0 or 32
    const float* hw = wsm + hw_i * (64 * WST);
    const float  bmain = (mode == 2) ? 0.f : Bv[head];
    const float  bpart = (mode == 2) ? 0.f : Bv[head + 4];
    const int    sidx  = (mode == 1) ? 64 : 65;

    for (int tile = bset; tile < ntiles; tile += nbper) {
        const long tok0 = (long)tile * TOK;
        __syncthreads();                 // protect xs from previous iteration
        const float* xg = x + tok0 * Ee;
        for (int idx = tid; idx < TOK * 66; idx += 256) {
            int t = idx / 66, c = idx - t * 66;
            int src = (c < 64) ? (x_off + c) : ((c == 64) ? 64 : 129);
            xs[t * XST + c] = xg[t * Ee + src];
        }
        __syncthreads();

        ull acc[8][4];
#pragma unroll
        for (int i = 0; i < 8; i++)
#pragma unroll
            for (int c = 0; c < 4; c++) acc[i][c] = 0ULL;

        const float* xsw = xs + (toff + g) * XST;
#pragma unroll 1
        for (int kc = 0; kc < 16; kc++) {
            ull w[16];
            const float* wp = hw + kc * 4 * WST + colg * 8;
#pragma unroll
            for (int kk = 0; kk < 4; kk++)
#pragma unroll
                for (int c = 0; c < 4; c++)
                    w[kk * 4 + c] = *(const ull*)(wp + kk * WST + 2 * c);
#pragma unroll
            for (int i = 0; i < 8; i++) {
                const float4 xv = *(const float4*)(xsw + i * 4 * XST + kc * 4);
                float xa[4] = {xv.x, xv.y, xv.z, xv.w};
#pragma unroll
                for (int kk = 0; kk < 4; kk++) {
                    ull xx = splat2(xa[kk]);
#pragma unroll
                    for (int c = 0; c < 4; c++) fma2(acc[i][c], w[kk * 4 + c], xx);
                }
            }
        }

        // ---- main head row: cols 64..129 via STG.64, shfl stitches odd offset
#pragma unroll
        for (int i = 0; i < 8; i++) {
            const int t = toff + i * 4 + g;
            float myhi = __uint_as_float((uint32_t)(acc[i][3] >> 32));
            float prev = __shfl_up_sync(0xffffffffu, myhi, 1);
            if (colg == 0) prev = 0.f;
            ull* op = (ull*)(ob + (tok0 + t) * HE + head * Ee + 64 + colg * 8);
            op[0] = pack2(__float_as_uint(prev), (uint32_t)acc[i][0]);
            op[1] = pack2((uint32_t)(acc[i][0] >> 32), (uint32_t)acc[i][1]);
            op[2] = pack2((uint32_t)(acc[i][1] >> 32), (uint32_t)acc[i][2]);
            op[3] = pack2((uint32_t)(acc[i][2] >> 32), (uint32_t)acc[i][3]);
            if (colg == 7) {
                float b = bmain * xs[t * XST + 65];   // s_last * B[h] (0 for v)
                op[4] = pack2((uint32_t)(acc[i][3] >> 32), __float_as_uint(b));
            }
        }
        // zeros cols 0..63 of this warp's 32 main rows
        for (int idx = lane; idx < 32 * 32; idx += 32) {
            int t = toff + (idx >> 5), m = idx & 31;
            ((ull*)(ob + (tok0 + t) * HE + head * Ee))[m] = 0ULL;
        }
        // partner rows (q/k only): zero except col 65
        if (mode < 2) {
            for (int idx = lane; idx < 32 * 65; idx += 32) {
                int t = toff + idx / 65, m = idx % 65;
                ull v = 0ULL;
                if (m == 32) {
                    float s = xs[t * XST + sidx];
                    v = (ull)__float_as_uint(s * bpart) << 32;  // (col64=0, col65=s*b)
                }
                ((ull*)(ob + (tok0 + t) * HE + (head + 4) * Ee))[m] = v;
            }
        }
    }
}

extern "C" void kernel_launch(void* const* d_in, const int* in_sizes, int n_in,
                              void* d_out, int out_size)
{
    const float* x  = (const float*)d_in[0];
    const float* Mq = (const float*)d_in[1];
    const float* Bq = (const float*)d_in[2];
    const float* Mk = (const float*)d_in[3];
    const float* Bk = (const float*)d_in[4];
    const float* Mv = (const float*)d_in[5];
    float* out = (float*)d_out;

    const int ntok   = in_sizes[0] / Ee;            // 32768
    const int ntiles = (ntok + TOK - 1) / TOK;      // 512
    const long S     = (long)out_size / 3;

    const int grid  = 296;                          // 74 blocks per config
    const int nbper = grid / 4;
    const int smem  = (NH * 64 * WST + TOK * XST) * (int)sizeof(float); // 84,992 B
    cudaFuncSetAttribute(fused_kernel, cudaFuncAttributeMaxDynamicSharedMemorySize, smem);

    fused_kernel<<<grid, 256, smem>>>(x, Mq, Bq, Mk, Bk, Mv, out, S, ntiles, nbper);
}